// round 16
// baseline (speedup 1.0000x reference)
#include <cuda_runtime.h>
#include <cuda_bf16.h>

#define TICKS   1000
#define TPAD    1024        // TICKS rounded up to 32 — sim chunks read the pad
#define NTAPS   49
#define KW      7
#define OUT_CH  128
#define MAXD    14          // 6 + min(stride,8)
#define MAXC    (MAXD*MAXD) // 196

// ---- scratch (no allocations allowed) ----
__device__ __align__(16) float d_hist[MAXC * TICKS];   // hist[cls][t]

__device__ __forceinline__ int imin(int a, int b) { return a < b ? a : b; }

// ------------------------------------------------------------------
// 1) event scatter into hist[cls][t]. (unchanged — ~5us)
// ------------------------------------------------------------------
__global__ void __launch_bounds__(1024) scatter_kernel(
    const int* __restrict__ tk, const int* __restrict__ xs,
    const int* __restrict__ ys, const float* __restrict__ vs,
    const int* __restrict__ sp, int n)
{
    __shared__ float sh[4 * 1024];             // [hot][t], t padded to 1024
    const int stride = *sp;
    const int D  = 6 + imin(stride, 8);
    const bool s2 = (stride == 2);

    if (s2) {
        for (int i = threadIdx.x; i < 4 * 1024; i += blockDim.x) sh[i] = 0.f;
        __syncthreads();
    }

    const int tid = blockIdx.x * blockDim.x + threadIdx.x;
    const int nth = gridDim.x * blockDim.x;

    auto proc = [&](int t, int x, int y, float v) {
        if (s2) {
            if (x >= 6 && y >= 6) {              // hot: smem ATOMS
                int h = ((y & 1) << 1) | (x & 1);
                atomicAdd(&sh[h * 1024 + t], v);
            } else {                             // cold (~9%): global RED
                int cx = (x < 6) ? x : 6 + (x & 1);
                int cy = (y < 6) ? y : 6 + (y & 1);
                atomicAdd(&d_hist[(cy * 8 + cx) * TICKS + t], v);
            }
        } else {
            int cx = (x < 6) ? x : 6 + imin(x % stride, 7);
            int cy = (y < 6) ? y : 6 + imin(y % stride, 7);
            atomicAdd(&d_hist[(cy * D + cx) * TICKS + t], v);
        }
    };

    const int n4 = n >> 2;
    const int4*   t4 = reinterpret_cast<const int4*>(tk);
    const int4*   x4 = reinterpret_cast<const int4*>(xs);
    const int4*   y4 = reinterpret_cast<const int4*>(ys);
    const float4* v4 = reinterpret_cast<const float4*>(vs);

    for (int i = tid; i < n4; i += nth) {
        int4   a = t4[i];
        int4   b = x4[i];
        int4   c = y4[i];
        float4 w = v4[i];
        proc(a.x, b.x, c.x, w.x);
        proc(a.y, b.y, c.y, w.y);
        proc(a.z, b.z, c.z, w.z);
        proc(a.w, b.w, c.w, w.w);
    }
    for (int i = (n4 << 2) + tid; i < n; i += nth)
        proc(tk[i], xs[i], ys[i], vs[i]);

    if (s2) {
        __syncthreads();
        for (int i = threadIdx.x; i < 4 * TICKS; i += blockDim.x) {
            int h = i / TICKS, t = i - h * TICKS;
            float val = sh[h * 1024 + t];
            if (val != 0.f) {
                int cls = 54 + 8 * (h >> 1) + (h & 1);
                atomicAdd(&d_hist[cls * TICKS + t], val);
            }
        }
    }
}

// ------------------------------------------------------------------
// 2) fused drive + Izhikevich sim. One 1024-thread block per channel.
//    Phase C: PRED-FREE recurrence loop. R15 post-mortem: the binding
//    cycle ran through FSETP (13cyc pred production) via the u spike
//    increment. Fix: carry un (u without DP) and fold the DP term into
//    a constant offset on the spike candidate:
//      hun    = fmaf(-h, un, Ih)                       [pred-free]
//      cand_n = rq + hun                                [== old value
//                 exactly when no prior spike]
//      cand_s = DSPQ2 + hun, DSPQ2 = VRS+QC*h + (-h*DP) [constant]
//      vnew   = pprev ? cand_s : cand_n   [FSEL; pred resolved @13,
//                 inputs @20 -> pred fully hidden]
//    Binding cycle: vnew -> t1n -> un -> hun -> cand -> FSEL ~24cyc.
//    Rounding deltas only at spike ticks (~1e-6 class, already proven
//    in-margin in R14/R15).
// ------------------------------------------------------------------
__global__ void __launch_bounds__(1024) sim_kernel(
    const float* __restrict__ w, const int* __restrict__ sp,
    float* __restrict__ out)
{
    __shared__ float wc[MAXC];
    __shared__ float sg[TPAD + 4];

    const int c   = blockIdx.x;
    const int tid = threadIdx.x;
    const int stride = *sp;
    const int D = 6 + imin(stride, 8);
    const int C = D * D;

    // ---- Phase A: class weights for this channel ----
    if (tid < C) {
        const int cls = tid;
        const int cy = cls / D, cx = cls % D;
        int sx, lx, sy, ly;
        if (cx < 6) { sx = cx % stride; lx = cx; } else { sx = cx - 6; lx = 6; }
        if (cy < 6) { sy = cy % stride; ly = cy; } else { sy = cy - 6; ly = 6; }
        float acc = 0.f;
        for (int ky = sy; ky <= ly; ky += stride)
            for (int kx = sx; kx <= lx; kx += stride)
                acc += w[c * NTAPS + ky * KW + kx];
        wc[cls] = acc;
    }
    for (int i = tid; i < TPAD + 4; i += blockDim.x) sg[i] = 0.f;
    __syncthreads();

    // ---- Phase B: sg[t] = dot(wc, hist[:, t-1]) for t in [1, TICKS] ----
    if (tid >= 1 && tid <= TICKS) {
        const int tm1 = tid - 1;
        const float* __restrict__ hp = d_hist + tm1;
        float acc = 0.f;
        #pragma unroll 16
        for (int cls = 0; cls < C; ++cls)
            acc = fmaf(wc[cls], __ldg(&hp[cls * TICKS]), acc);
        sg[tid] = acc;                            // 1-tick synaptic delay
    }
    __syncthreads();

    // ---- Phase C: serial sim, warp 0 only ----
    if (tid >= 32) return;
    const int lane = tid;

    float* __restrict__ ospk = out + c * TICKS;
    float* __restrict__ ovtr = out + OUT_CH * TICKS + c * TICKS;

    const float decay = 0.9f;                        // 1 - dt/tau_fall
    const float h     = (float)(0.001 / 150.0);      // dt / C
    const float negh  = -h;
    const float Kp = 1.2f, VR = -75.f, VT = -45.f;
    const float AP = 0.01f, BP = 5.f, VP = 50.f;
    const float DP = 130.f, VRS = -56.f, IIN = 350.f, DT = 0.001f;
    const float QC    = 1.2f * (VRS - VR) * (VRS - VT);
    const float Kph   = Kp * h;
    const float K1    = AP * BP * DT;                // 5e-5
    const float K2    = 1.0f - AP * DT;              // 1 - 1e-5
    const float IINh  = IIN * h;
    const float HDP   = -h * DP;                     // -h*DP (constant)
    const float DSPQ  = VRS + QC * h;                // spike base
    const float DSPQ2 = DSPQ + HDP;                  // spike base w/ DP term

    // carries: v = vnew(t-1); un = u(t-1) WITHOUT the DP increment;
    // pprev = spike bit of t-1. u(t-1) = un + (pprev ? DP : 0).
    float v = VR, un = 0.f, S = 0.f;
    bool  pprev = false;

    for (int t0 = 0; t0 < TICKS; t0 += 32) {
        float keepv = 0.f, keeps = 0.f;
        #pragma unroll
        for (int i = 0; i < 32; ++i) {
            // drive chain (independent of v,u — runs ahead)
            float gt = sg[t0 + i];                   // pad ticks harmless
            S = fmaf(S, decay, gt);                  // S*decay + g
            float Ih = fmaf(S, h, IINh);             // (IIN+S)*h
            // pred-free u-join
            float hun = fmaf(negh, un, Ih);          // Ih - h*un
            // drive-free v-quadratic (hidden under u-path)
            float t1 = v - VR;
            float t2 = v - VT;
            float m2 = Kph * t1;
            float rq = fmaf(m2, t2, v);
            // two pred-free candidates, one FSEL
            float cand_n = rq + hun;                 // no prior spike
            float cand_s = DSPQ2 + hun;              // prior spike (const base)
            float vnew = pprev ? cand_s : cand_n;    // pred resolved @13 << 20
            // u bookkeeping (off the binding loop)
            float dpadd = pprev ? DP : 0.0f;
            float uprev = un + dpadd;                // full u(t-1)
            float uK2 = uprev * K2;
            float t1n = vnew - VR;
            un = fmaf(K1, t1n, uK2);                 // un(t), pred-free
            bool  sp_ = vnew >= VP;                  // off-loop now
            float spf   = sp_ ? 1.f : 0.f;
            float vpost = sp_ ? VRS : vnew;          // recorded value
            v = vnew; pprev = sp_;
            keepv = (lane == i) ? vpost : keepv;
            keeps = (lane == i) ? spf   : keeps;
        }
        int t = t0 + lane;
        if (t < TICKS) {                             // guard: 1000 % 32 != 0
            ospk[t] = keeps;
            ovtr[t] = keepv;
        }
    }
}

// ------------------------------------------------------------------
extern "C" void kernel_launch(void* const* d_in, const int* in_sizes, int n_in,
                              void* d_out, int out_size)
{
    const int*   tk = (const int*)  d_in[0];   // spike_ticks
    const int*   xs = (const int*)  d_in[1];   // spike_x
    const int*   ys = (const int*)  d_in[2];   // spike_y
    const float* vs = (const float*)d_in[3];   // spike_values
    const float* w  = (const float*)d_in[4];   // weights [128,49]
    const int*   sp = (const int*)  d_in[5];   // stride
    const int    n  = in_sizes[0];

    void* hist_ptr = nullptr;
    cudaGetSymbolAddress(&hist_ptr, d_hist);
    cudaMemsetAsync(hist_ptr, 0, sizeof(float) * MAXC * TICKS);   // memset node

    scatter_kernel<<<148, 1024>>>(tk, xs, ys, vs, sp, n);
    sim_kernel<<<OUT_CH, 1024>>>(w, sp, (float*)d_out);
}

// round 17
// speedup vs baseline: 1.4284x; 1.4284x over previous
#include <cuda_runtime.h>
#include <cuda_bf16.h>

#define TICKS   1000
#define TPAD    1024        // TICKS rounded up to 32 — sim chunks read the pad
#define NTAPS   49
#define KW      7
#define OUT_CH  128
#define MAXD    14          // 6 + min(stride,8)
#define MAXC    (MAXD*MAXD) // 196

// ---- scratch (no allocations allowed) ----
__device__ __align__(16) float d_hist[MAXC * TICKS];   // hist[cls][t]

__device__ __forceinline__ int imin(int a, int b) { return a < b ? a : b; }

// ------------------------------------------------------------------
// 1) event scatter into hist[cls][t]. (unchanged — ~5us)
// ------------------------------------------------------------------
__global__ void __launch_bounds__(1024) scatter_kernel(
    const int* __restrict__ tk, const int* __restrict__ xs,
    const int* __restrict__ ys, const float* __restrict__ vs,
    const int* __restrict__ sp, int n)
{
    __shared__ float sh[4 * 1024];             // [hot][t], t padded to 1024
    const int stride = *sp;
    const int D  = 6 + imin(stride, 8);
    const bool s2 = (stride == 2);

    if (s2) {
        for (int i = threadIdx.x; i < 4 * 1024; i += blockDim.x) sh[i] = 0.f;
        __syncthreads();
    }

    const int tid = blockIdx.x * blockDim.x + threadIdx.x;
    const int nth = gridDim.x * blockDim.x;

    auto proc = [&](int t, int x, int y, float v) {
        if (s2) {
            if (x >= 6 && y >= 6) {              // hot: smem ATOMS
                int h = ((y & 1) << 1) | (x & 1);
                atomicAdd(&sh[h * 1024 + t], v);
            } else {                             // cold (~9%): global RED
                int cx = (x < 6) ? x : 6 + (x & 1);
                int cy = (y < 6) ? y : 6 + (y & 1);
                atomicAdd(&d_hist[(cy * 8 + cx) * TICKS + t], v);
            }
        } else {
            int cx = (x < 6) ? x : 6 + imin(x % stride, 7);
            int cy = (y < 6) ? y : 6 + imin(y % stride, 7);
            atomicAdd(&d_hist[(cy * D + cx) * TICKS + t], v);
        }
    };

    const int n4 = n >> 2;
    const int4*   t4 = reinterpret_cast<const int4*>(tk);
    const int4*   x4 = reinterpret_cast<const int4*>(xs);
    const int4*   y4 = reinterpret_cast<const int4*>(ys);
    const float4* v4 = reinterpret_cast<const float4*>(vs);

    for (int i = tid; i < n4; i += nth) {
        int4   a = t4[i];
        int4   b = x4[i];
        int4   c = y4[i];
        float4 w = v4[i];
        proc(a.x, b.x, c.x, w.x);
        proc(a.y, b.y, c.y, w.y);
        proc(a.z, b.z, c.z, w.z);
        proc(a.w, b.w, c.w, w.w);
    }
    for (int i = (n4 << 2) + tid; i < n; i += nth)
        proc(tk[i], xs[i], ys[i], vs[i]);

    if (s2) {
        __syncthreads();
        for (int i = threadIdx.x; i < 4 * TICKS; i += blockDim.x) {
            int h = i / TICKS, t = i - h * TICKS;
            float val = sh[h * 1024 + t];
            if (val != 0.f) {
                int cls = 54 + 8 * (h >> 1) + (h & 1);
                atomicAdd(&d_hist[cls * TICKS + t], val);
            }
        }
    }
}

// ------------------------------------------------------------------
// 2) fused drive + Izhikevich sim. One 1024-thread block per channel.
//    Phase C: pred-free binding loop with the pred correction joining
//    the u-chain LAST (R16 regressed by joining it FIRST):
//      inner = fmaf(K2, un(t-1), cdK(t-1))   [previous-tick values only]
//      un    = fmaf(K1, vnew-VR, inner)      [pred-free]
//      hun   = fmaf(-h, un, Ih)              [pred-free]
//      vnew' = pprev ? (DSPQ2 + hun) : (rq + hun)
//        DSPQ2 = VRS + QC*h - h*DP  [constant, carries the -h*d term]
//        cdK   = pprev ? DP*K2 : 0  [computed off-chain, used next tick]
//    Binding loop: vnew -> t1n(4) -> un(8) -> hun(12) -> cand(16) ->
//    FSEL(21) = ~21cyc/tick (R15: 29, R16: 41). Non-spike path value-
//    identical to R15; spike ticks add one ~1e-7 rounding (safe class).
// ------------------------------------------------------------------
__global__ void __launch_bounds__(1024) sim_kernel(
    const float* __restrict__ w, const int* __restrict__ sp,
    float* __restrict__ out)
{
    __shared__ float wc[MAXC];
    __shared__ float sg[TPAD + 4];

    const int c   = blockIdx.x;
    const int tid = threadIdx.x;
    const int stride = *sp;
    const int D = 6 + imin(stride, 8);
    const int C = D * D;

    // ---- Phase A: class weights for this channel ----
    if (tid < C) {
        const int cls = tid;
        const int cy = cls / D, cx = cls % D;
        int sx, lx, sy, ly;
        if (cx < 6) { sx = cx % stride; lx = cx; } else { sx = cx - 6; lx = 6; }
        if (cy < 6) { sy = cy % stride; ly = cy; } else { sy = cy - 6; ly = 6; }
        float acc = 0.f;
        for (int ky = sy; ky <= ly; ky += stride)
            for (int kx = sx; kx <= lx; kx += stride)
                acc += w[c * NTAPS + ky * KW + kx];
        wc[cls] = acc;
    }
    for (int i = tid; i < TPAD + 4; i += blockDim.x) sg[i] = 0.f;
    __syncthreads();

    // ---- Phase B: sg[t] = dot(wc, hist[:, t-1]) for t in [1, TICKS] ----
    if (tid >= 1 && tid <= TICKS) {
        const int tm1 = tid - 1;
        const float* __restrict__ hp = d_hist + tm1;
        float acc = 0.f;
        #pragma unroll 16
        for (int cls = 0; cls < C; ++cls)
            acc = fmaf(wc[cls], __ldg(&hp[cls * TICKS]), acc);
        sg[tid] = acc;                            // 1-tick synaptic delay
    }
    __syncthreads();

    // ---- Phase C: serial sim, warp 0 only ----
    if (tid >= 32) return;
    const int lane = tid;

    float* __restrict__ ospk = out + c * TICKS;
    float* __restrict__ ovtr = out + OUT_CH * TICKS + c * TICKS;

    const float decay = 0.9f;                        // 1 - dt/tau_fall
    const float h     = (float)(0.001 / 150.0);      // dt / C
    const float negh  = -h;
    const float Kp = 1.2f, VR = -75.f, VT = -45.f;
    const float AP = 0.01f, BP = 5.f, VP = 50.f;
    const float DP = 130.f, VRS = -56.f, IIN = 350.f, DT = 0.001f;
    const float QC    = 1.2f * (VRS - VR) * (VRS - VT);
    const float Kph   = Kp * h;
    const float K1    = AP * BP * DT;                // 5e-5
    const float K2    = 1.0f - AP * DT;              // 1 - 1e-5
    const float IINh  = IIN * h;
    const float D2K   = DP * K2;                     // DP pre-scaled by K2
    const float DSPQ2 = (VRS + QC * h) + (-h * DP);  // spike base + d-term

    // carries: v = vnew(t-1); un = u(t-1) w/o DP kick; cdK = K2-scaled DP
    // kick of (t-1); pprev = spike bit of (t-1).
    float v = VR, un = 0.f, cdK = 0.f, S = 0.f;
    bool  pprev = false;

    for (int t0 = 0; t0 < TICKS; t0 += 32) {
        float keepv = 0.f, keeps = 0.f;
        #pragma unroll
        for (int i = 0; i < 32; ++i) {
            // drive chain (independent of v,u — runs ahead)
            float gt = sg[t0 + i];                   // pad ticks harmless
            S = fmaf(S, decay, gt);                  // S*decay + g
            float Ih = fmaf(S, h, IINh);             // (IIN+S)*h
            // u pre-chain from PREVIOUS tick's values (ready early)
            float inner = fmaf(K2, un, cdK);         // K2*un + K2*d
            // pred-free u join of u(t-1):
            float hun = fmaf(negh, un, Ih);          // Ih - h*un(t-1)
            // drive-free v-quadratic (parallel, hidden)
            float t1 = v - VR;
            float t2 = v - VT;
            float m2 = Kph * t1;
            float rq = fmaf(m2, t2, v);
            // candidates + single FSEL (pred resolved 13cyc ago)
            float cand_n = rq + hun;                 // no prior spike
            float cand_s = DSPQ2 + hun;              // prior spike
            float vnew = pprev ? cand_s : cand_n;
            // u-chain: joins pred correction LAST (via inner, next tick)
            float t1n = vnew - VR;
            un = fmaf(K1, t1n, inner);               // un(t), pred-free
            bool  sp_ = vnew >= VP;                  // off the binding loop
            cdK = sp_ ? D2K : 0.0f;                  // for next tick's inner
            float spf   = sp_ ? 1.f : 0.f;
            float vpost = sp_ ? VRS : vnew;          // recorded value
            v = vnew; pprev = sp_;
            keepv = (lane == i) ? vpost : keepv;
            keeps = (lane == i) ? spf   : keeps;
        }
        int t = t0 + lane;
        if (t < TICKS) {                             // guard: 1000 % 32 != 0
            ospk[t] = keeps;
            ovtr[t] = keepv;
        }
    }
}

// ------------------------------------------------------------------
extern "C" void kernel_launch(void* const* d_in, const int* in_sizes, int n_in,
                              void* d_out, int out_size)
{
    const int*   tk = (const int*)  d_in[0];   // spike_ticks
    const int*   xs = (const int*)  d_in[1];   // spike_x
    const int*   ys = (const int*)  d_in[2];   // spike_y
    const float* vs = (const float*)d_in[3];   // spike_values
    const float* w  = (const float*)d_in[4];   // weights [128,49]
    const int*   sp = (const int*)  d_in[5];   // stride
    const int    n  = in_sizes[0];

    void* hist_ptr = nullptr;
    cudaGetSymbolAddress(&hist_ptr, d_hist);
    cudaMemsetAsync(hist_ptr, 0, sizeof(float) * MAXC * TICKS);   // memset node

    scatter_kernel<<<148, 1024>>>(tk, xs, ys, vs, sp, n);
    sim_kernel<<<OUT_CH, 1024>>>(w, sp, (float*)d_out);
}